// round 5
// baseline (speedup 1.0000x reference)
#include <cuda_runtime.h>
#include <cstdint>

// Problem constants (fixed by the dataset)
constexpr int D      = 128;     // embed size
constexpr int H      = 256;     // hidden size
constexpr int NODES  = 8192;    // 2*B
constexpr int BP     = 4096;    // pairs
constexpr int T_EDG  = NODES * 32;
constexpr int K1     = 3 * D;   // 384
constexpr int K2     = 2 * H;   // 512

// Scratch (all GEMM inputs stored pre-converted to tf32-in-fp32 container)
__device__ float g_A1[(size_t)NODES * K1];
__device__ float g_node[(size_t)NODES * H];
__device__ float g_W1[K1 * H];
__device__ float g_Wr[K2 * H];
__device__ float g_b1[H];

__device__ __forceinline__ uint32_t f2tf32(float f) {
    uint32_t u;
    asm("cvt.rna.tf32.f32 %0, %1;" : "=r"(u) : "f"(f));
    return u;
}
__device__ __forceinline__ float cvt_tf32(float f) {
    return __uint_as_float(f2tf32(f));
}

// ---------------------------------------------------------------------------
// Kernel 1: gather + segment mean (one WARP per node) + fused weight prep.
// Weight prep: 262144 threads each convert <=1 element of W1/Wr (+ b1).
// ---------------------------------------------------------------------------
__global__ void gather_mean(const float* __restrict__ E, const float* __restrict__ R,
                            const int* __restrict__ ents,
                            const int* __restrict__ nent,
                            const int* __restrict__ nrel,
                            const int* __restrict__ offs,
                            const float* __restrict__ Wt,
                            const float* __restrict__ Wn,
                            const float* __restrict__ Wr,
                            const float* __restrict__ bt,
                            const float* __restrict__ bn) {
    // ---- fused weight prep (independent of gather work) ----
    {
        const int gt = blockIdx.x * blockDim.x + threadIdx.x;
        const int wt_sz = D * H;          // 32768
        const int w1_sz = K1 * H;         // 98304
        if (gt < w1_sz) {
            g_W1[gt] = cvt_tf32(gt < wt_sz ? Wt[gt] : Wn[gt - wt_sz]);
        } else if (gt < w1_sz + K2 * H) {
            const int i = gt - w1_sz;
            g_Wr[i] = cvt_tf32(Wr[i]);
        }
        if (gt < H) g_b1[gt] = bt[gt] + bn[gt];
    }

    const int gw   = (blockIdx.x * blockDim.x + threadIdx.x) >> 5;  // node
    const int lane = threadIdx.x & 31;
    if (gw >= NODES) return;

    const int start = offs[gw];
    const int end   = (gw + 1 < NODES) ? offs[gw + 1] : T_EDG;
    const int cnt   = end - start;

    const float4* E4 = (const float4*)E;
    const float4* R4 = (const float4*)R;

    float4 se = make_float4(0.f, 0.f, 0.f, 0.f);
    float4 sr = make_float4(0.f, 0.f, 0.f, 0.f);

    if (cnt == 32) {
        const int iE = nent[start + lane];
        const int iR = nrel[start + lane];
        #pragma unroll 8
        for (int j = 0; j < 32; j++) {
            const int ie = __shfl_sync(0xffffffffu, iE, j);
            const int ir = __shfl_sync(0xffffffffu, iR, j);
            float4 ve = __ldg(&E4[(size_t)ie * (D / 4) + lane]);
            float4 vr = __ldg(&R4[(size_t)ir * (D / 4) + lane]);
            se.x += ve.x; se.y += ve.y; se.z += ve.z; se.w += ve.w;
            sr.x += vr.x; sr.y += vr.y; sr.z += vr.z; sr.w += vr.w;
        }
    } else {
        for (int base = start; base < end; base += 32) {
            const int rem = end - base;
            const int n   = rem < 32 ? rem : 32;
            const int iE  = (lane < rem) ? nent[base + lane] : 0;
            const int iR  = (lane < rem) ? nrel[base + lane] : 0;
            #pragma unroll 4
            for (int j = 0; j < n; j++) {
                const int ie = __shfl_sync(0xffffffffu, iE, j);
                const int ir = __shfl_sync(0xffffffffu, iR, j);
                float4 ve = __ldg(&E4[(size_t)ie * (D / 4) + lane]);
                float4 vr = __ldg(&R4[(size_t)ir * (D / 4) + lane]);
                se.x += ve.x; se.y += ve.y; se.z += ve.z; se.w += ve.w;
                sr.x += vr.x; sr.y += vr.y; sr.z += vr.z; sr.w += vr.w;
            }
        }
    }
    const float inv = 1.0f / (float)(cnt > 0 ? cnt : 1);
    float4 e = __ldg(&E4[(size_t)ents[gw] * (D / 4) + lane]);

    float* row = g_A1 + (size_t)gw * K1;
    float4 o0, o1, o2;
    o0.x = cvt_tf32(e.x);        o0.y = cvt_tf32(e.y);
    o0.z = cvt_tf32(e.z);        o0.w = cvt_tf32(e.w);
    o1.x = cvt_tf32(se.x * inv); o1.y = cvt_tf32(se.y * inv);
    o1.z = cvt_tf32(se.z * inv); o1.w = cvt_tf32(se.w * inv);
    o2.x = cvt_tf32(sr.x * inv); o2.y = cvt_tf32(sr.y * inv);
    o2.z = cvt_tf32(sr.z * inv); o2.w = cvt_tf32(sr.w * inv);
    *(float4*)(row + lane * 4)         = o0;
    *(float4*)(row + D + lane * 4)     = o1;
    *(float4*)(row + 2 * D + lane * 4) = o2;
}

// ---------------------------------------------------------------------------
__device__ __forceinline__ void cp16(void* smem, const void* gmem) {
    uint32_t s = (uint32_t)__cvta_generic_to_shared(smem);
    asm volatile("cp.async.cg.shared.global [%0], [%1], 16;" :: "r"(s), "l"(gmem));
}

// ---------------------------------------------------------------------------
// TF32 tensor-core GEMM, BK=32, 3-stage cp.async pipeline, one sync per tile.
// C[M,N] = relu(A[M,K] @ B[K,N] + bias[N]); inputs pre-rounded to tf32.
// ---------------------------------------------------------------------------
template <int BM, int BN, int WM, int WN, bool CVT_OUT>
__global__ void __launch_bounds__(WM * WN * 32)
mma_gemm_bias_relu(const float* __restrict__ A, const float* __restrict__ B,
                   const float* __restrict__ bias, float* __restrict__ C,
                   int M, int N, int K) {
    constexpr int BK      = 32;
    constexpr int STAGES  = 3;
    constexpr int THREADS = WM * WN * 32;
    constexpr int TMW     = BM / WM;
    constexpr int TNW     = BN / WN;
    constexpr int MF      = TMW / 16;
    constexpr int NF      = TNW / 8;
    constexpr int SAS     = BK + 4;          // 36: conflict-free frag loads
    constexpr int SBS     = BN + 8;          // mod 32 == 8: conflict-free
    constexpr int A_CH    = (BM * (BK / 4)) / THREADS;
    constexpr int B_CH    = (BK * (BN / 4)) / THREADS;
    constexpr int A_SZ    = BM * SAS;
    constexpr int B_SZ    = BK * SBS;

    extern __shared__ float smem[];
    float* sAb = smem;
    float* sBb = smem + STAGES * A_SZ;

    const int tid  = threadIdx.x;
    const int wid  = tid >> 5;
    const int lane = tid & 31;
    const int grp  = lane >> 2;
    const int tg   = lane & 3;
    const int wm   = wid % WM;
    const int wn   = wid / WM;

    const int bx = blockIdx.x;
    const int by = blockIdx.y;

    const float* Ag = A + (size_t)by * BM * K;
    const float* Bg = B + (size_t)bx * BN;

    float acc[MF][NF][4];
    #pragma unroll
    for (int i = 0; i < MF; i++)
        #pragma unroll
        for (int j = 0; j < NF; j++)
            #pragma unroll
            for (int c = 0; c < 4; c++) acc[i][j][c] = 0.f;

    auto issue = [&](int t, int stg) {
        float* sA = sAb + stg * A_SZ;
        float* sB = sBb + stg * B_SZ;
        const float* At = Ag + t * BK;
        #pragma unroll
        for (int l = 0; l < A_CH; l++) {
            int idx = tid + l * THREADS;
            int row = idx >> 3;              // BK/4 = 8 chunks per row
            int c4  = idx & 7;
            cp16(&sA[row * SAS + c4 * 4], At + (size_t)row * K + c4 * 4);
        }
        const float* Bt = Bg + (size_t)t * BK * N;
        #pragma unroll
        for (int l = 0; l < B_CH; l++) {
            int idx = tid + l * THREADS;
            int row = idx / (BN / 4);
            int c4  = idx % (BN / 4);
            cp16(&sB[row * SBS + c4 * 4], Bt + (size_t)row * N + c4 * 4);
        }
    };

    const int ntiles = K / BK;

    #pragma unroll
    for (int s = 0; s < STAGES - 1; s++) {
        if (s < ntiles) issue(s, s);
        asm volatile("cp.async.commit_group;");
    }

    for (int t = 0; t < ntiles; t++) {
        asm volatile("cp.async.wait_group %0;" :: "n"(STAGES - 2));
        __syncthreads();
        const int nt = t + STAGES - 1;
        if (nt < ntiles) issue(nt, nt % STAGES);
        asm volatile("cp.async.commit_group;");

        const float* sA = sAb + (t % STAGES) * A_SZ;
        const float* sB = sBb + (t % STAGES) * B_SZ;
        #pragma unroll
        for (int ks = 0; ks < BK; ks += 8) {
            uint32_t af[MF][4];
            #pragma unroll
            for (int i = 0; i < MF; i++) {
                int rb = wm * TMW + i * 16 + grp;
                af[i][0] = __float_as_uint(sA[(rb + 0) * SAS + ks + tg]);
                af[i][1] = __float_as_uint(sA[(rb + 8) * SAS + ks + tg]);
                af[i][2] = __float_as_uint(sA[(rb + 0) * SAS + ks + tg + 4]);
                af[i][3] = __float_as_uint(sA[(rb + 8) * SAS + ks + tg + 4]);
            }
            uint32_t bf[NF][2];
            #pragma unroll
            for (int j = 0; j < NF; j++) {
                int cb = wn * TNW + j * 8 + grp;
                bf[j][0] = __float_as_uint(sB[(ks + tg) * SBS + cb]);
                bf[j][1] = __float_as_uint(sB[(ks + tg + 4) * SBS + cb]);
            }
            #pragma unroll
            for (int i = 0; i < MF; i++)
                #pragma unroll
                for (int j = 0; j < NF; j++) {
                    asm volatile(
                        "mma.sync.aligned.m16n8k8.row.col.f32.tf32.tf32.f32 "
                        "{%0,%1,%2,%3}, {%4,%5,%6,%7}, {%8,%9}, {%0,%1,%2,%3};"
                        : "+f"(acc[i][j][0]), "+f"(acc[i][j][1]),
                          "+f"(acc[i][j][2]), "+f"(acc[i][j][3])
                        : "r"(af[i][0]), "r"(af[i][1]), "r"(af[i][2]), "r"(af[i][3]),
                          "r"(bf[j][0]), "r"(bf[j][1]));
                }
        }
    }

    // epilogue: bias + relu (+ optional tf32 rounding for the next GEMM)
    #pragma unroll
    for (int i = 0; i < MF; i++) {
        const int r0 = by * BM + wm * TMW + i * 16 + grp;
        #pragma unroll
        for (int j = 0; j < NF; j++) {
            const int c = bx * BN + wn * TNW + j * 8 + tg * 2;
            const float b0 = bias[c], b1 = bias[c + 1];
            float2 v0, v1;
            v0.x = fmaxf(acc[i][j][0] + b0, 0.f);
            v0.y = fmaxf(acc[i][j][1] + b1, 0.f);
            v1.x = fmaxf(acc[i][j][2] + b0, 0.f);
            v1.y = fmaxf(acc[i][j][3] + b1, 0.f);
            if (CVT_OUT) {
                v0.x = cvt_tf32(v0.x); v0.y = cvt_tf32(v0.y);
                v1.x = cvt_tf32(v1.x); v1.y = cvt_tf32(v1.y);
            }
            *(float2*)(C + (size_t)r0 * N + c)       = v0;
            *(float2*)(C + (size_t)(r0 + 8) * N + c) = v1;
        }
    }
}

// ---------------------------------------------------------------------------
extern "C" void kernel_launch(void* const* d_in, const int* in_sizes, int n_in,
                              void* d_out, int out_size) {
    const float* E    = (const float*)d_in[0];
    const float* R    = (const float*)d_in[1];
    const float* Wt   = (const float*)d_in[2];
    const float* bt   = (const float*)d_in[3];
    const float* Wn   = (const float*)d_in[4];
    const float* bn   = (const float*)d_in[5];
    const float* Wr   = (const float*)d_in[6];
    const float* br   = (const float*)d_in[7];
    const int*   ents = (const int*)d_in[8];
    const int*   nent = (const int*)d_in[9];
    const int*   nrel = (const int*)d_in[10];
    const int*   offs = (const int*)d_in[11];
    float* out = (float*)d_out;

    float *A1, *node, *W1, *Wr32, *b1;
    cudaGetSymbolAddress((void**)&A1,   g_A1);
    cudaGetSymbolAddress((void**)&node, g_node);
    cudaGetSymbolAddress((void**)&W1,   g_W1);
    cudaGetSymbolAddress((void**)&Wr32, g_Wr);
    cudaGetSymbolAddress((void**)&b1,   g_b1);

    // dynamic smem: 3 stages * (32*36 + 32*72) floats = 41472 bytes
    constexpr int SMEM = 3 * (32 * 36 + 32 * 72) * 4;
    cudaFuncSetAttribute(mma_gemm_bias_relu<32, 64, 2, 2, true>,
                         cudaFuncAttributeMaxDynamicSharedMemorySize, SMEM);
    cudaFuncSetAttribute(mma_gemm_bias_relu<32, 64, 2, 2, false>,
                         cudaFuncAttributeMaxDynamicSharedMemorySize, SMEM);

    // 1) gather + segment mean (+ fused weight prep) -> A1 [8192, 384] (tf32)
    gather_mean<<<NODES / 8, 256>>>(E, R, ents, nent, nrel, offs,
                                    Wt, Wn, Wr, bt, bn);

    // 2) node = tf32(relu(A1 @ W1 + b1))  [8192, 256]  grid 4 x 256 = 1024 CTAs
    mma_gemm_bias_relu<32, 64, 2, 2, true>
        <<<dim3(H / 64, NODES / 32), 128, SMEM>>>(A1, W1, b1, node, NODES, H, K1);

    // 3) out = relu(node.view(4096,512) @ Wr + br)     grid 4 x 128 = 512 CTAs
    mma_gemm_bias_relu<32, 64, 2, 2, false>
        <<<dim3(H / 64, BP / 32), 128, SMEM>>>(node, Wr32, br, out, BP, H, K2);
}

// round 6
// speedup vs baseline: 1.0257x; 1.0257x over previous
#include <cuda_runtime.h>
#include <cstdint>

// Problem constants (fixed by the dataset)
constexpr int D      = 128;     // embed size
constexpr int H      = 256;     // hidden size
constexpr int NODES  = 8192;    // 2*B
constexpr int BP     = 4096;    // pairs
constexpr int T_EDG  = NODES * 32;
constexpr int K1     = 3 * D;   // 384
constexpr int K2     = 2 * H;   // 512

// Scratch (all GEMM inputs stored pre-converted to tf32-in-fp32 container)
__device__ float g_A1[(size_t)NODES * K1];
__device__ float g_node[(size_t)NODES * H];
__device__ float g_W1[K1 * H];
__device__ float g_Wr[K2 * H];
__device__ float g_b1[H];

__device__ __forceinline__ uint32_t f2tf32(float f) {
    uint32_t u;
    asm("cvt.rna.tf32.f32 %0, %1;" : "=r"(u) : "f"(f));
    return u;
}
__device__ __forceinline__ float cvt_tf32(float f) {
    return __uint_as_float(f2tf32(f));
}

// ---------------------------------------------------------------------------
// Kernel 1: gather + segment mean, TWO warps per node (+ fused weight prep).
//   even warp (E-warp): self entity + mean of 32 neighbor-entity rows
//                       -> writes A1 row cols [0, 2D)
//   odd  warp (R-warp): mean of 32 relation rows (L2-resident table)
//                       -> writes A1 row cols [2D, 3D)
// One accumulator per warp -> low regs -> high occupancy -> high DRAM MLP.
// ---------------------------------------------------------------------------
__global__ void gather_mean(const float* __restrict__ E, const float* __restrict__ R,
                            const int* __restrict__ ents,
                            const int* __restrict__ nent,
                            const int* __restrict__ nrel,
                            const int* __restrict__ offs,
                            const float* __restrict__ Wt,
                            const float* __restrict__ Wn,
                            const float* __restrict__ Wr,
                            const float* __restrict__ bt,
                            const float* __restrict__ bn) {
    // ---- fused weight prep (independent of gather work) ----
    {
        const int gt = blockIdx.x * blockDim.x + threadIdx.x;
        const int wt_sz = D * H;          // 32768
        const int w1_sz = K1 * H;         // 98304
        if (gt < w1_sz) {
            g_W1[gt] = cvt_tf32(gt < wt_sz ? Wt[gt] : Wn[gt - wt_sz]);
        } else if (gt < w1_sz + K2 * H) {
            const int i = gt - w1_sz;
            g_Wr[i] = cvt_tf32(Wr[i]);
        }
        if (gt < H) g_b1[gt] = bt[gt] + bn[gt];
    }

    const int gw   = (blockIdx.x * blockDim.x + threadIdx.x) >> 5;
    const int lane = threadIdx.x & 31;
    const int node = gw >> 1;
    const bool isE = (gw & 1) == 0;
    if (node >= NODES) return;

    const int start = offs[node];
    const int end   = (node + 1 < NODES) ? offs[node + 1] : T_EDG;
    const int cnt   = end - start;
    const float inv = 1.0f / (float)(cnt > 0 ? cnt : 1);

    float* row = g_A1 + (size_t)node * K1;

    if (isE) {
        const float4* E4 = (const float4*)E;
        float4 s = make_float4(0.f, 0.f, 0.f, 0.f);
        if (cnt == 32) {
            const int idx = nent[start + lane];
            #pragma unroll 8
            for (int j = 0; j < 32; j++) {
                const int ie = __shfl_sync(0xffffffffu, idx, j);
                float4 v = __ldg(&E4[(size_t)ie * (D / 4) + lane]);
                s.x += v.x; s.y += v.y; s.z += v.z; s.w += v.w;
            }
        } else {
            for (int base = start; base < end; base += 32) {
                const int rem = end - base;
                const int n   = rem < 32 ? rem : 32;
                const int idx = (lane < rem) ? nent[base + lane] : 0;
                #pragma unroll 4
                for (int j = 0; j < n; j++) {
                    const int ie = __shfl_sync(0xffffffffu, idx, j);
                    float4 v = __ldg(&E4[(size_t)ie * (D / 4) + lane]);
                    s.x += v.x; s.y += v.y; s.z += v.z; s.w += v.w;
                }
            }
        }
        float4 e = __ldg(&E4[(size_t)ents[node] * (D / 4) + lane]);
        float4 o0, o1;
        o0.x = cvt_tf32(e.x);       o0.y = cvt_tf32(e.y);
        o0.z = cvt_tf32(e.z);       o0.w = cvt_tf32(e.w);
        o1.x = cvt_tf32(s.x * inv); o1.y = cvt_tf32(s.y * inv);
        o1.z = cvt_tf32(s.z * inv); o1.w = cvt_tf32(s.w * inv);
        *(float4*)(row + lane * 4)     = o0;
        *(float4*)(row + D + lane * 4) = o1;
    } else {
        const float4* R4 = (const float4*)R;
        float4 s = make_float4(0.f, 0.f, 0.f, 0.f);
        if (cnt == 32) {
            const int idx = nrel[start + lane];
            #pragma unroll 8
            for (int j = 0; j < 32; j++) {
                const int ir = __shfl_sync(0xffffffffu, idx, j);
                float4 v = __ldg(&R4[(size_t)ir * (D / 4) + lane]);
                s.x += v.x; s.y += v.y; s.z += v.z; s.w += v.w;
            }
        } else {
            for (int base = start; base < end; base += 32) {
                const int rem = end - base;
                const int n   = rem < 32 ? rem : 32;
                const int idx = (lane < rem) ? nrel[base + lane] : 0;
                #pragma unroll 4
                for (int j = 0; j < n; j++) {
                    const int ir = __shfl_sync(0xffffffffu, idx, j);
                    float4 v = __ldg(&R4[(size_t)ir * (D / 4) + lane]);
                    s.x += v.x; s.y += v.y; s.z += v.z; s.w += v.w;
                }
            }
        }
        float4 o2;
        o2.x = cvt_tf32(s.x * inv); o2.y = cvt_tf32(s.y * inv);
        o2.z = cvt_tf32(s.z * inv); o2.w = cvt_tf32(s.w * inv);
        *(float4*)(row + 2 * D + lane * 4) = o2;
    }
}

// ---------------------------------------------------------------------------
__device__ __forceinline__ void cp16(void* smem, const void* gmem) {
    uint32_t s = (uint32_t)__cvta_generic_to_shared(smem);
    asm volatile("cp.async.cg.shared.global [%0], [%1], 16;" :: "r"(s), "l"(gmem));
}

// ---------------------------------------------------------------------------
// TF32 tensor-core GEMM, BK=32, 3-stage cp.async pipeline, one sync per tile.
// C[M,N] = relu(A[M,K] @ B[K,N] + bias[N]); inputs pre-rounded to tf32.
// ---------------------------------------------------------------------------
template <int BM, int BN, int WM, int WN, bool CVT_OUT>
__global__ void __launch_bounds__(WM * WN * 32)
mma_gemm_bias_relu(const float* __restrict__ A, const float* __restrict__ B,
                   const float* __restrict__ bias, float* __restrict__ C,
                   int M, int N, int K) {
    constexpr int BK      = 32;
    constexpr int STAGES  = 3;
    constexpr int THREADS = WM * WN * 32;
    constexpr int TMW     = BM / WM;
    constexpr int TNW     = BN / WN;
    constexpr int MF      = TMW / 16;
    constexpr int NF      = TNW / 8;
    constexpr int SAS     = BK + 4;          // 36: conflict-free frag loads
    constexpr int SBS     = BN + 8;          // mod 32 == 8: conflict-free
    constexpr int A_CH    = (BM * (BK / 4)) / THREADS;
    constexpr int B_CH    = (BK * (BN / 4)) / THREADS;
    constexpr int A_SZ    = BM * SAS;
    constexpr int B_SZ    = BK * SBS;

    extern __shared__ float smem[];
    float* sAb = smem;
    float* sBb = smem + STAGES * A_SZ;

    const int tid  = threadIdx.x;
    const int wid  = tid >> 5;
    const int lane = tid & 31;
    const int grp  = lane >> 2;
    const int tg   = lane & 3;
    const int wm   = wid % WM;
    const int wn   = wid / WM;

    const int bx = blockIdx.x;
    const int by = blockIdx.y;

    const float* Ag = A + (size_t)by * BM * K;
    const float* Bg = B + (size_t)bx * BN;

    float acc[MF][NF][4];
    #pragma unroll
    for (int i = 0; i < MF; i++)
        #pragma unroll
        for (int j = 0; j < NF; j++)
            #pragma unroll
            for (int c = 0; c < 4; c++) acc[i][j][c] = 0.f;

    auto issue = [&](int t, int stg) {
        float* sA = sAb + stg * A_SZ;
        float* sB = sBb + stg * B_SZ;
        const float* At = Ag + t * BK;
        #pragma unroll
        for (int l = 0; l < A_CH; l++) {
            int idx = tid + l * THREADS;
            int row = idx >> 3;              // BK/4 = 8 chunks per row
            int c4  = idx & 7;
            cp16(&sA[row * SAS + c4 * 4], At + (size_t)row * K + c4 * 4);
        }
        const float* Bt = Bg + (size_t)t * BK * N;
        #pragma unroll
        for (int l = 0; l < B_CH; l++) {
            int idx = tid + l * THREADS;
            int row = idx / (BN / 4);
            int c4  = idx % (BN / 4);
            cp16(&sB[row * SBS + c4 * 4], Bt + (size_t)row * N + c4 * 4);
        }
    };

    const int ntiles = K / BK;

    #pragma unroll
    for (int s = 0; s < STAGES - 1; s++) {
        if (s < ntiles) issue(s, s);
        asm volatile("cp.async.commit_group;");
    }

    for (int t = 0; t < ntiles; t++) {
        asm volatile("cp.async.wait_group %0;" :: "n"(STAGES - 2));
        __syncthreads();
        const int nt = t + STAGES - 1;
        if (nt < ntiles) issue(nt, nt % STAGES);
        asm volatile("cp.async.commit_group;");

        const float* sA = sAb + (t % STAGES) * A_SZ;
        const float* sB = sBb + (t % STAGES) * B_SZ;
        #pragma unroll
        for (int ks = 0; ks < BK; ks += 8) {
            uint32_t af[MF][4];
            #pragma unroll
            for (int i = 0; i < MF; i++) {
                int rb = wm * TMW + i * 16 + grp;
                af[i][0] = __float_as_uint(sA[(rb + 0) * SAS + ks + tg]);
                af[i][1] = __float_as_uint(sA[(rb + 8) * SAS + ks + tg]);
                af[i][2] = __float_as_uint(sA[(rb + 0) * SAS + ks + tg + 4]);
                af[i][3] = __float_as_uint(sA[(rb + 8) * SAS + ks + tg + 4]);
            }
            uint32_t bf[NF][2];
            #pragma unroll
            for (int j = 0; j < NF; j++) {
                int cb = wn * TNW + j * 8 + grp;
                bf[j][0] = __float_as_uint(sB[(ks + tg) * SBS + cb]);
                bf[j][1] = __float_as_uint(sB[(ks + tg + 4) * SBS + cb]);
            }
            #pragma unroll
            for (int i = 0; i < MF; i++)
                #pragma unroll
                for (int j = 0; j < NF; j++) {
                    asm volatile(
                        "mma.sync.aligned.m16n8k8.row.col.f32.tf32.tf32.f32 "
                        "{%0,%1,%2,%3}, {%4,%5,%6,%7}, {%8,%9}, {%0,%1,%2,%3};"
                        : "+f"(acc[i][j][0]), "+f"(acc[i][j][1]),
                          "+f"(acc[i][j][2]), "+f"(acc[i][j][3])
                        : "r"(af[i][0]), "r"(af[i][1]), "r"(af[i][2]), "r"(af[i][3]),
                          "r"(bf[j][0]), "r"(bf[j][1]));
                }
        }
    }

    // epilogue: bias + relu (+ optional tf32 rounding for the next GEMM)
    #pragma unroll
    for (int i = 0; i < MF; i++) {
        const int r0 = by * BM + wm * TMW + i * 16 + grp;
        #pragma unroll
        for (int j = 0; j < NF; j++) {
            const int c = bx * BN + wn * TNW + j * 8 + tg * 2;
            const float b0 = bias[c], b1 = bias[c + 1];
            float2 v0, v1;
            v0.x = fmaxf(acc[i][j][0] + b0, 0.f);
            v0.y = fmaxf(acc[i][j][1] + b1, 0.f);
            v1.x = fmaxf(acc[i][j][2] + b0, 0.f);
            v1.y = fmaxf(acc[i][j][3] + b1, 0.f);
            if (CVT_OUT) {
                v0.x = cvt_tf32(v0.x); v0.y = cvt_tf32(v0.y);
                v1.x = cvt_tf32(v1.x); v1.y = cvt_tf32(v1.y);
            }
            *(float2*)(C + (size_t)r0 * N + c)       = v0;
            *(float2*)(C + (size_t)(r0 + 8) * N + c) = v1;
        }
    }
}

// ---------------------------------------------------------------------------
extern "C" void kernel_launch(void* const* d_in, const int* in_sizes, int n_in,
                              void* d_out, int out_size) {
    const float* E    = (const float*)d_in[0];
    const float* R    = (const float*)d_in[1];
    const float* Wt   = (const float*)d_in[2];
    const float* bt   = (const float*)d_in[3];
    const float* Wn   = (const float*)d_in[4];
    const float* bn   = (const float*)d_in[5];
    const float* Wr   = (const float*)d_in[6];
    const float* br   = (const float*)d_in[7];
    const int*   ents = (const int*)d_in[8];
    const int*   nent = (const int*)d_in[9];
    const int*   nrel = (const int*)d_in[10];
    const int*   offs = (const int*)d_in[11];
    float* out = (float*)d_out;

    float *A1, *node, *W1, *Wr32, *b1;
    cudaGetSymbolAddress((void**)&A1,   g_A1);
    cudaGetSymbolAddress((void**)&node, g_node);
    cudaGetSymbolAddress((void**)&W1,   g_W1);
    cudaGetSymbolAddress((void**)&Wr32, g_Wr);
    cudaGetSymbolAddress((void**)&b1,   g_b1);

    // dynamic smem: 3 stages * (64*36 + 32*72) floats = 55296 bytes
    constexpr int SMEM = 3 * (64 * 36 + 32 * 72) * 4;
    cudaFuncSetAttribute(mma_gemm_bias_relu<64, 64, 2, 2, true>,
                         cudaFuncAttributeMaxDynamicSharedMemorySize, SMEM);
    cudaFuncSetAttribute(mma_gemm_bias_relu<64, 64, 2, 2, false>,
                         cudaFuncAttributeMaxDynamicSharedMemorySize, SMEM);

    // 1) gather + segment mean (+ fused weight prep), 2 warps/node
    //    16384 warps -> 2048 CTAs x 256 threads
    gather_mean<<<NODES / 4, 256>>>(E, R, ents, nent, nrel, offs,
                                    Wt, Wn, Wr, bt, bn);

    // 2) node = tf32(relu(A1 @ W1 + b1))  [8192, 256]  grid 4 x 128 = 512 CTAs
    mma_gemm_bias_relu<64, 64, 2, 2, true>
        <<<dim3(H / 64, NODES / 64), 128, SMEM>>>(A1, W1, b1, node, NODES, H, K1);

    // 3) out = relu(node.view(4096,512) @ Wr + br)     grid 4 x 64 = 256 CTAs
    mma_gemm_bias_relu<64, 64, 2, 2, false>
        <<<dim3(H / 64, BP / 64), 128, SMEM>>>(node, Wr32, br, out, BP, H, K2);
}

// round 7
// speedup vs baseline: 1.0538x; 1.0274x over previous
#include <cuda_runtime.h>
#include <cstdint>

// Problem constants (fixed by the dataset)
constexpr int D      = 128;     // embed size
constexpr int H      = 256;     // hidden size
constexpr int NODES  = 8192;    // 2*B
constexpr int BP     = 4096;    // pairs
constexpr int T_EDG  = NODES * 32;
constexpr int K1     = 3 * D;   // 384
constexpr int K2     = 2 * H;   // 512

// Scratch
__device__ float g_A1[(size_t)NODES * K1];
__device__ float g_W1[K1 * H];
__device__ float g_Wr[K2 * H];
__device__ float g_b1[H];

__device__ __forceinline__ uint32_t f2tf32(float f) {
    uint32_t u;
    asm("cvt.rna.tf32.f32 %0, %1;" : "=r"(u) : "f"(f));
    return u;
}
__device__ __forceinline__ float cvt_tf32(float f) {
    return __uint_as_float(f2tf32(f));
}

// ---------------------------------------------------------------------------
// Kernel 1: gather + segment mean, TWO warps per node (+ fused weight prep).
// ---------------------------------------------------------------------------
__global__ void gather_mean(const float* __restrict__ E, const float* __restrict__ R,
                            const int* __restrict__ ents,
                            const int* __restrict__ nent,
                            const int* __restrict__ nrel,
                            const int* __restrict__ offs,
                            const float* __restrict__ Wt,
                            const float* __restrict__ Wn,
                            const float* __restrict__ Wr,
                            const float* __restrict__ bt,
                            const float* __restrict__ bn) {
    // ---- fused weight prep ----
    {
        const int gt = blockIdx.x * blockDim.x + threadIdx.x;
        const int wt_sz = D * H;          // 32768
        const int w1_sz = K1 * H;         // 98304
        if (gt < w1_sz) {
            g_W1[gt] = cvt_tf32(gt < wt_sz ? Wt[gt] : Wn[gt - wt_sz]);
        } else if (gt < w1_sz + K2 * H) {
            const int i = gt - w1_sz;
            g_Wr[i] = cvt_tf32(Wr[i]);
        }
        if (gt < H) g_b1[gt] = bt[gt] + bn[gt];
    }

    const int gw   = (blockIdx.x * blockDim.x + threadIdx.x) >> 5;
    const int lane = threadIdx.x & 31;
    const int node = gw >> 1;
    const bool isE = (gw & 1) == 0;
    if (node >= NODES) return;

    const int start = offs[node];
    const int end   = (node + 1 < NODES) ? offs[node + 1] : T_EDG;
    const int cnt   = end - start;
    const float inv = 1.0f / (float)(cnt > 0 ? cnt : 1);

    float* row = g_A1 + (size_t)node * K1;

    if (isE) {
        const float4* E4 = (const float4*)E;
        float4 s = make_float4(0.f, 0.f, 0.f, 0.f);
        if (cnt == 32) {
            const int idx = nent[start + lane];
            #pragma unroll 8
            for (int j = 0; j < 32; j++) {
                const int ie = __shfl_sync(0xffffffffu, idx, j);
                float4 v = __ldg(&E4[(size_t)ie * (D / 4) + lane]);
                s.x += v.x; s.y += v.y; s.z += v.z; s.w += v.w;
            }
        } else {
            for (int base = start; base < end; base += 32) {
                const int rem = end - base;
                const int n   = rem < 32 ? rem : 32;
                const int idx = (lane < rem) ? nent[base + lane] : 0;
                #pragma unroll 4
                for (int j = 0; j < n; j++) {
                    const int ie = __shfl_sync(0xffffffffu, idx, j);
                    float4 v = __ldg(&E4[(size_t)ie * (D / 4) + lane]);
                    s.x += v.x; s.y += v.y; s.z += v.z; s.w += v.w;
                }
            }
        }
        float4 e = __ldg(&E4[(size_t)ents[node] * (D / 4) + lane]);
        float4 o0, o1;
        o0.x = cvt_tf32(e.x);       o0.y = cvt_tf32(e.y);
        o0.z = cvt_tf32(e.z);       o0.w = cvt_tf32(e.w);
        o1.x = cvt_tf32(s.x * inv); o1.y = cvt_tf32(s.y * inv);
        o1.z = cvt_tf32(s.z * inv); o1.w = cvt_tf32(s.w * inv);
        *(float4*)(row + lane * 4)     = o0;
        *(float4*)(row + D + lane * 4) = o1;
    } else {
        const float4* R4 = (const float4*)R;
        float4 s = make_float4(0.f, 0.f, 0.f, 0.f);
        if (cnt == 32) {
            const int idx = nrel[start + lane];
            #pragma unroll 8
            for (int j = 0; j < 32; j++) {
                const int ir = __shfl_sync(0xffffffffu, idx, j);
                float4 v = __ldg(&R4[(size_t)ir * (D / 4) + lane]);
                s.x += v.x; s.y += v.y; s.z += v.z; s.w += v.w;
            }
        } else {
            for (int base = start; base < end; base += 32) {
                const int rem = end - base;
                const int n   = rem < 32 ? rem : 32;
                const int idx = (lane < rem) ? nrel[base + lane] : 0;
                #pragma unroll 4
                for (int j = 0; j < n; j++) {
                    const int ir = __shfl_sync(0xffffffffu, idx, j);
                    float4 v = __ldg(&R4[(size_t)ir * (D / 4) + lane]);
                    s.x += v.x; s.y += v.y; s.z += v.z; s.w += v.w;
                }
            }
        }
        float4 o2;
        o2.x = cvt_tf32(s.x * inv); o2.y = cvt_tf32(s.y * inv);
        o2.z = cvt_tf32(s.z * inv); o2.w = cvt_tf32(s.w * inv);
        *(float4*)(row + 2 * D + lane * 4) = o2;
    }
}

// ---------------------------------------------------------------------------
__device__ __forceinline__ void cp16(void* smem, const void* gmem) {
    uint32_t s = (uint32_t)__cvta_generic_to_shared(smem);
    asm volatile("cp.async.cg.shared.global [%0], [%1], 16;" :: "r"(s), "l"(gmem));
}
__device__ __forceinline__ void mma_tf32(float* a4, uint32_t a0, uint32_t a1,
                                         uint32_t a2, uint32_t a3,
                                         uint32_t b0, uint32_t b1) {
    asm volatile(
        "mma.sync.aligned.m16n8k8.row.col.f32.tf32.tf32.f32 "
        "{%0,%1,%2,%3}, {%4,%5,%6,%7}, {%8,%9}, {%0,%1,%2,%3};"
        : "+f"(a4[0]), "+f"(a4[1]), "+f"(a4[2]), "+f"(a4[3])
        : "r"(a0), "r"(a1), "r"(a2), "r"(a3), "r"(b0), "r"(b1));
}

// ---------------------------------------------------------------------------
// Fused MLP kernel: one CTA per 64 node-rows (= 32 pairs), 512 threads.
// Phase 1: nodeTile[64,256] = tf32(relu(A1[64rows,384] @ W1 + b1)) -> SMEM
// Phase 2: out[32pairs,256] = relu(pairview(nodeTile)[32,512] @ Wr + br)
// ---------------------------------------------------------------------------
constexpr int BK     = 32;
constexpr int STAGES = 3;
constexpr int BM     = 64;
constexpr int BN     = 256;     // full H
constexpr int SAS    = BK + 4;            // 36
constexpr int SBS    = BN + 8;            // 264
constexpr int SN     = 258;               // node tile stride (see theory)
constexpr int A_SZ   = BM * SAS;          // 2304
constexpr int B_SZ   = BK * SBS;          // 8448
constexpr int FUSED_SMEM_FLOATS = BM * SN + STAGES * A_SZ + STAGES * B_SZ;
constexpr int FUSED_SMEM = FUSED_SMEM_FLOATS * 4;   // 195072 B

__global__ void __launch_bounds__(512)
fused_mlp(const float* __restrict__ A1full, const float* __restrict__ W1,
          const float* __restrict__ b1g, const float* __restrict__ Wr,
          const float* __restrict__ br, float* __restrict__ out) {
    constexpr int THREADS = 512;

    extern __shared__ float smem[];
    float* sN  = smem;                         // [64][SN]
    float* sAb = smem + BM * SN;               // STAGES * A_SZ
    float* sBb = sAb + STAGES * A_SZ;          // STAGES * B_SZ

    const int tid  = threadIdx.x;
    const int wid  = tid >> 5;
    const int lane = tid & 31;
    const int grp  = lane >> 2;
    const int tg   = lane & 3;
    const int by   = blockIdx.x;

    const float* Ag = A1full + (size_t)by * BM * K1;

    // ---- loaders (shared by both phases; A only in phase 1) ----
    auto issueA = [&](int t, int stg) {
        float* sA = sAb + stg * A_SZ;
        const float* At = Ag + t * BK;
        // (64 rows * 8 chunks) / 512 threads = 1 chunk/thread
        int row = tid >> 3;
        int c4  = tid & 7;
        cp16(&sA[row * SAS + c4 * 4], At + (size_t)row * K1 + c4 * 4);
    };
    auto issueB = [&](const float* Bsrc, int t, int stg) {
        float* sB = sBb + stg * B_SZ;
        const float* Bt = Bsrc + (size_t)t * BK * BN;
        #pragma unroll
        for (int l = 0; l < 4; l++) {          // (32*64)/512 = 4
            int idx = tid + l * THREADS;
            int row = idx >> 6;                // BN/4 = 64
            int c4  = idx & 63;
            cp16(&sB[row * SBS + c4 * 4], Bt + (size_t)row * BN + c4 * 4);
        }
    };

    // =========================== PHASE 1 ===================================
    // warps: WM=2 x WN=8; warp tile 32x32 (MF=2, NF=4)
    {
        const int wm = wid & 1;
        const int wn = wid >> 1;

        float acc[2][4][4];
        #pragma unroll
        for (int i = 0; i < 2; i++)
            #pragma unroll
            for (int j = 0; j < 4; j++)
                #pragma unroll
                for (int c = 0; c < 4; c++) acc[i][j][c] = 0.f;

        const int nt1 = K1 / BK;   // 12
        #pragma unroll
        for (int s = 0; s < STAGES - 1; s++) {
            issueA(s, s); issueB(W1, s, s);
            asm volatile("cp.async.commit_group;");
        }

        for (int t = 0; t < nt1; t++) {
            asm volatile("cp.async.wait_group %0;" :: "n"(STAGES - 2));
            __syncthreads();
            const int nt = t + STAGES - 1;
            if (nt < nt1) { issueA(nt, nt % STAGES); issueB(W1, nt, nt % STAGES); }
            asm volatile("cp.async.commit_group;");

            const float* sA = sAb + (t % STAGES) * A_SZ;
            const float* sB = sBb + (t % STAGES) * B_SZ;
            #pragma unroll
            for (int ks = 0; ks < BK; ks += 8) {
                uint32_t af[2][4];
                #pragma unroll
                for (int i = 0; i < 2; i++) {
                    int rb = wm * 32 + i * 16 + grp;
                    af[i][0] = __float_as_uint(sA[(rb + 0) * SAS + ks + tg]);
                    af[i][1] = __float_as_uint(sA[(rb + 8) * SAS + ks + tg]);
                    af[i][2] = __float_as_uint(sA[(rb + 0) * SAS + ks + tg + 4]);
                    af[i][3] = __float_as_uint(sA[(rb + 8) * SAS + ks + tg + 4]);
                }
                uint32_t bf[4][2];
                #pragma unroll
                for (int j = 0; j < 4; j++) {
                    int cb = wn * 32 + j * 8 + grp;
                    bf[j][0] = __float_as_uint(sB[(ks + tg) * SBS + cb]);
                    bf[j][1] = __float_as_uint(sB[(ks + tg + 4) * SBS + cb]);
                }
                #pragma unroll
                for (int i = 0; i < 2; i++)
                    #pragma unroll
                    for (int j = 0; j < 4; j++)
                        mma_tf32(acc[i][j], af[i][0], af[i][1], af[i][2], af[i][3],
                                 bf[j][0], bf[j][1]);
            }
        }

        // drain pipeline before reusing sB for phase 2
        asm volatile("cp.async.wait_group 0;");

        // epilogue 1: bias + relu + tf32 -> sN
        #pragma unroll
        for (int i = 0; i < 2; i++) {
            const int r0 = wm * 32 + i * 16 + grp;
            #pragma unroll
            for (int j = 0; j < 4; j++) {
                const int c = wn * 32 + j * 8 + tg * 2;
                const float b0 = b1g[c], b1v = b1g[c + 1];
                float2 v0, v1;
                v0.x = cvt_tf32(fmaxf(acc[i][j][0] + b0, 0.f));
                v0.y = cvt_tf32(fmaxf(acc[i][j][1] + b1v, 0.f));
                v1.x = cvt_tf32(fmaxf(acc[i][j][2] + b0, 0.f));
                v1.y = cvt_tf32(fmaxf(acc[i][j][3] + b1v, 0.f));
                *(float2*)(&sN[(r0 + 0) * SN + c]) = v0;
                *(float2*)(&sN[(r0 + 8) * SN + c]) = v1;
            }
        }
        __syncthreads();
    }

    // =========================== PHASE 2 ===================================
    // out tile: 32 pairs x 256. A(p,k) = sN[(2p + (k>=256)) * SN + (k&255)]
    // warps: WM2=2 x WN2=8; warp tile 16x32 (MF=1, NF=4)
    {
        const int wm2 = wid & 1;
        const int wn2 = wid >> 1;

        float acc[4][4];
        #pragma unroll
        for (int j = 0; j < 4; j++)
            #pragma unroll
            for (int c = 0; c < 4; c++) acc[j][c] = 0.f;

        const int nt2 = K2 / BK;   // 16
        #pragma unroll
        for (int s = 0; s < STAGES - 1; s++) {
            issueB(Wr, s, s);
            asm volatile("cp.async.commit_group;");
        }

        for (int t = 0; t < nt2; t++) {
            asm volatile("cp.async.wait_group %0;" :: "n"(STAGES - 2));
            __syncthreads();
            const int nt = t + STAGES - 1;
            if (nt < nt2) issueB(Wr, nt, nt % STAGES);
            asm volatile("cp.async.commit_group;");

            const float* sB = sBb + (t % STAGES) * B_SZ;
            const int kbase = t * BK;
            #pragma unroll
            for (int ks = 0; ks < BK; ks += 8) {
                const int k  = kbase + ks;
                const int h  = (k >= 256) ? 1 : 0;
                const int kk = k & 255;
                const int p  = wm2 * 16 + grp;           // pair row in tile
                uint32_t a0 = __float_as_uint(sN[(2 * (p + 0) + h) * SN + kk + tg]);
                uint32_t a1 = __float_as_uint(sN[(2 * (p + 8) + h) * SN + kk + tg]);
                uint32_t a2 = __float_as_uint(sN[(2 * (p + 0) + h) * SN + kk + tg + 4]);
                uint32_t a3 = __float_as_uint(sN[(2 * (p + 8) + h) * SN + kk + tg + 4]);
                uint32_t bf[4][2];
                #pragma unroll
                for (int j = 0; j < 4; j++) {
                    int cb = wn2 * 32 + j * 8 + grp;
                    bf[j][0] = __float_as_uint(sB[(ks + tg) * SBS + cb]);
                    bf[j][1] = __float_as_uint(sB[(ks + tg + 4) * SBS + cb]);
                }
                #pragma unroll
                for (int j = 0; j < 4; j++)
                    mma_tf32(acc[j], a0, a1, a2, a3, bf[j][0], bf[j][1]);
            }
        }

        // epilogue 2: bias + relu -> gmem
        const int prow = by * 32 + wm2 * 16 + grp;
        #pragma unroll
        for (int j = 0; j < 4; j++) {
            const int c = wn2 * 32 + j * 8 + tg * 2;
            const float b0 = br[c], b1v = br[c + 1];
            float2 v0, v1;
            v0.x = fmaxf(acc[j][0] + b0, 0.f);
            v0.y = fmaxf(acc[j][1] + b1v, 0.f);
            v1.x = fmaxf(acc[j][2] + b0, 0.f);
            v1.y = fmaxf(acc[j][3] + b1v, 0.f);
            *(float2*)(out + (size_t)(prow + 0) * H + c) = v0;
            *(float2*)(out + (size_t)(prow + 8) * H + c) = v1;
        }
    }
}

// ---------------------------------------------------------------------------
extern "C" void kernel_launch(void* const* d_in, const int* in_sizes, int n_in,
                              void* d_out, int out_size) {
    const float* E    = (const float*)d_in[0];
    const float* R    = (const float*)d_in[1];
    const float* Wt   = (const float*)d_in[2];
    const float* bt   = (const float*)d_in[3];
    const float* Wn   = (const float*)d_in[4];
    const float* bn   = (const float*)d_in[5];
    const float* Wr   = (const float*)d_in[6];
    const float* br   = (const float*)d_in[7];
    const int*   ents = (const int*)d_in[8];
    const int*   nent = (const int*)d_in[9];
    const int*   nrel = (const int*)d_in[10];
    const int*   offs = (const int*)d_in[11];
    float* out = (float*)d_out;

    float *A1, *W1, *Wr32, *b1;
    cudaGetSymbolAddress((void**)&A1,   g_A1);
    cudaGetSymbolAddress((void**)&W1,   g_W1);
    cudaGetSymbolAddress((void**)&Wr32, g_Wr);
    cudaGetSymbolAddress((void**)&b1,   g_b1);

    cudaFuncSetAttribute(fused_mlp,
                         cudaFuncAttributeMaxDynamicSharedMemorySize, FUSED_SMEM);

    // 1) gather + segment mean (+ fused weight prep), 2 warps/node
    gather_mean<<<NODES / 4, 256>>>(E, R, ents, nent, nrel, offs,
                                    Wt, Wn, Wr, bt, bn);

    // 2+3) fused node-MLP + pair-MLP, 128 CTAs x 512 threads
    fused_mlp<<<NODES / BM, 512, FUSED_SMEM>>>(A1, W1, b1, Wr32, br, out);
}

// round 8
// speedup vs baseline: 1.0580x; 1.0040x over previous
#include <cuda_runtime.h>
#include <cstdint>

// Problem constants (fixed by the dataset)
constexpr int D      = 128;     // embed size
constexpr int H      = 256;     // hidden size
constexpr int NODES  = 8192;    // 2*B
constexpr int BP     = 4096;    // pairs
constexpr int T_EDG  = NODES * 32;
constexpr int K1     = 3 * D;   // 384
constexpr int K2     = 2 * H;   // 512

// Scratch
__device__ float g_A1[(size_t)NODES * K1];
__device__ float g_W1p[K1 * H];   // W1 packed in mma-fragment order
__device__ float g_Wrp[K2 * H];   // Wr packed in mma-fragment order
__device__ float g_b1[H];

__device__ __forceinline__ uint32_t f2tf32(float f) {
    uint32_t u;
    asm("cvt.rna.tf32.f32 %0, %1;" : "=r"(u) : "f"(f));
    return u;
}
__device__ __forceinline__ float cvt_tf32(float f) {
    return __uint_as_float(f2tf32(f));
}

// ---------------------------------------------------------------------------
// Packed weight layout (per BK=16 tile t):
//   dst = ((t*2 + ks)*32 + j)*64 + lane*2 + r
//   src = W[k][col],  k = t*16 + ks*8 + (lane&3) + r*4,  col = j*8 + (lane>>2)
// In the GEMM, a B fragment (b0,b1) for (ks, jfrag) is ONE float2 at
//   sB[((ks*32 + j)*64 + lane*2)].
// ---------------------------------------------------------------------------

// ---------------------------------------------------------------------------
// Kernel 1: gather + segment mean, TWO warps per node (+ fused weight pack).
// ---------------------------------------------------------------------------
__global__ void gather_mean(const float* __restrict__ E, const float* __restrict__ R,
                            const int* __restrict__ ents,
                            const int* __restrict__ nent,
                            const int* __restrict__ nrel,
                            const int* __restrict__ offs,
                            const float* __restrict__ Wt,
                            const float* __restrict__ Wn,
                            const float* __restrict__ Wr,
                            const float* __restrict__ bt,
                            const float* __restrict__ bn) {
    // ---- fused weight pack (independent of gather work) ----
    {
        const int gt = blockIdx.x * blockDim.x + threadIdx.x;
        const int w1_sz = K1 * H;         // 98304
        const int wr_sz = K2 * H;         // 131072
        if (gt < w1_sz) {
            const int r    = gt & 1;
            const int lane = (gt >> 1) & 31;
            const int j    = (gt >> 6) & 31;
            const int ks   = (gt >> 11) & 1;
            const int t    = gt >> 12;
            const int k    = t * 16 + ks * 8 + (lane & 3) + r * 4;
            const int col  = j * 8 + (lane >> 2);
            const float v  = (k < D) ? Wt[k * H + col] : Wn[(k - D) * H + col];
            g_W1p[gt] = cvt_tf32(v);
        } else if (gt < w1_sz + wr_sz) {
            const int idx  = gt - w1_sz;
            const int r    = idx & 1;
            const int lane = (idx >> 1) & 31;
            const int j    = (idx >> 6) & 31;
            const int ks   = (idx >> 11) & 1;
            const int t    = idx >> 12;
            const int k    = t * 16 + ks * 8 + (lane & 3) + r * 4;
            const int col  = j * 8 + (lane >> 2);
            g_Wrp[idx] = cvt_tf32(Wr[k * H + col]);
        }
        if (gt < H) g_b1[gt] = bt[gt] + bn[gt];
    }

    const int gw   = (blockIdx.x * blockDim.x + threadIdx.x) >> 5;
    const int lane = threadIdx.x & 31;
    const int node = gw >> 1;
    const bool isE = (gw & 1) == 0;
    if (node >= NODES) return;

    const int start = offs[node];
    const int end   = (node + 1 < NODES) ? offs[node + 1] : T_EDG;
    const int cnt   = end - start;
    const float inv = 1.0f / (float)(cnt > 0 ? cnt : 1);

    float* row = g_A1 + (size_t)node * K1;

    if (isE) {
        const float4* E4 = (const float4*)E;
        float4 s = make_float4(0.f, 0.f, 0.f, 0.f);
        if (cnt == 32) {
            const int idx = nent[start + lane];
            #pragma unroll 8
            for (int j = 0; j < 32; j++) {
                const int ie = __shfl_sync(0xffffffffu, idx, j);
                float4 v = __ldg(&E4[(size_t)ie * (D / 4) + lane]);
                s.x += v.x; s.y += v.y; s.z += v.z; s.w += v.w;
            }
        } else {
            for (int base = start; base < end; base += 32) {
                const int rem = end - base;
                const int n   = rem < 32 ? rem : 32;
                const int idx = (lane < rem) ? nent[base + lane] : 0;
                #pragma unroll 4
                for (int j = 0; j < n; j++) {
                    const int ie = __shfl_sync(0xffffffffu, idx, j);
                    float4 v = __ldg(&E4[(size_t)ie * (D / 4) + lane]);
                    s.x += v.x; s.y += v.y; s.z += v.z; s.w += v.w;
                }
            }
        }
        float4 e = __ldg(&E4[(size_t)ents[node] * (D / 4) + lane]);
        float4 o0, o1;
        o0.x = cvt_tf32(e.x);       o0.y = cvt_tf32(e.y);
        o0.z = cvt_tf32(e.z);       o0.w = cvt_tf32(e.w);
        o1.x = cvt_tf32(s.x * inv); o1.y = cvt_tf32(s.y * inv);
        o1.z = cvt_tf32(s.z * inv); o1.w = cvt_tf32(s.w * inv);
        *(float4*)(row + lane * 4)     = o0;
        *(float4*)(row + D + lane * 4) = o1;
    } else {
        const float4* R4 = (const float4*)R;
        float4 s = make_float4(0.f, 0.f, 0.f, 0.f);
        if (cnt == 32) {
            const int idx = nrel[start + lane];
            #pragma unroll 8
            for (int j = 0; j < 32; j++) {
                const int ir = __shfl_sync(0xffffffffu, idx, j);
                float4 v = __ldg(&R4[(size_t)ir * (D / 4) + lane]);
                s.x += v.x; s.y += v.y; s.z += v.z; s.w += v.w;
            }
        } else {
            for (int base = start; base < end; base += 32) {
                const int rem = end - base;
                const int n   = rem < 32 ? rem : 32;
                const int idx = (lane < rem) ? nrel[base + lane] : 0;
                #pragma unroll 4
                for (int j = 0; j < n; j++) {
                    const int ir = __shfl_sync(0xffffffffu, idx, j);
                    float4 v = __ldg(&R4[(size_t)ir * (D / 4) + lane]);
                    s.x += v.x; s.y += v.y; s.z += v.z; s.w += v.w;
                }
            }
        }
        float4 o2;
        o2.x = cvt_tf32(s.x * inv); o2.y = cvt_tf32(s.y * inv);
        o2.z = cvt_tf32(s.z * inv); o2.w = cvt_tf32(s.w * inv);
        *(float4*)(row + 2 * D + lane * 4) = o2;
    }
}

// ---------------------------------------------------------------------------
__device__ __forceinline__ void cp16(void* smem, const void* gmem) {
    uint32_t s = (uint32_t)__cvta_generic_to_shared(smem);
    asm volatile("cp.async.cg.shared.global [%0], [%1], 16;" :: "r"(s), "l"(gmem));
}
__device__ __forceinline__ void mma_tf32(float* a4, uint32_t a0, uint32_t a1,
                                         uint32_t a2, uint32_t a3,
                                         uint32_t b0, uint32_t b1) {
    asm volatile(
        "mma.sync.aligned.m16n8k8.row.col.f32.tf32.tf32.f32 "
        "{%0,%1,%2,%3}, {%4,%5,%6,%7}, {%8,%9}, {%0,%1,%2,%3};"
        : "+f"(a4[0]), "+f"(a4[1]), "+f"(a4[2]), "+f"(a4[3])
        : "r"(a0), "r"(a1), "r"(a2), "r"(a3), "r"(b0), "r"(b1));
}

// ---------------------------------------------------------------------------
// Fused MLP: one CTA per 32 node-rows (= 16 pairs), 256 threads, 256 CTAs.
// Phase 1: nodeTile[32,256] = tf32(relu(A1[32,384] @ W1 + b1)) -> SMEM
// Phase 2: out[16,256]      = relu(pairview(nodeTile)[16,512] @ Wr + br)
// B operands pre-packed in fragment order -> one LDS.64 per frag.
// ---------------------------------------------------------------------------
constexpr int BK     = 16;
constexpr int STAGES = 4;
constexpr int BM     = 32;
constexpr int BN     = 256;
constexpr int SAS    = BK + 4;             // 20
constexpr int SN     = 258;                // node-tile stride (conflict-free)
constexpr int A_SZ   = BM * SAS;           // 640
constexpr int B_SZ   = BK * BN;            // 4096 (packed, linear)
constexpr int FUSED_SMEM =
    (BM * SN + STAGES * A_SZ + STAGES * B_SZ) * 4;   // 108800 B

__global__ void __launch_bounds__(256, 2)
fused_mlp(const float* __restrict__ A1full, const float* __restrict__ W1p,
          const float* __restrict__ b1g, const float* __restrict__ Wrp,
          const float* __restrict__ br, float* __restrict__ out) {
    constexpr int THREADS = 256;

    extern __shared__ float smem[];
    float* sN  = smem;                      // [32][SN]
    float* sAb = smem + BM * SN;            // STAGES * A_SZ
    float* sBb = sAb + STAGES * A_SZ;       // STAGES * B_SZ

    const int tid  = threadIdx.x;
    const int wid  = tid >> 5;
    const int lane = tid & 31;
    const int grp  = lane >> 2;
    const int tg   = lane & 3;
    const int by   = blockIdx.x;

    const float* Ag = A1full + (size_t)by * BM * K1;

    auto issueA = [&](int t, int stg) {
        // 32 rows * 4 chunks = 128 chunks; threads 0..127
        if (tid < 128) {
            float* sA = sAb + stg * A_SZ;
            int row = tid >> 2;
            int c4  = tid & 3;
            cp16(&sA[row * SAS + c4 * 4],
                 Ag + (size_t)row * K1 + t * BK + c4 * 4);
        }
    };
    auto issueB = [&](const float* Wsrc, int t, int stg) {
        float* sB = sBb + stg * B_SZ;
        const float* src = Wsrc + (size_t)t * B_SZ;
        #pragma unroll
        for (int l = 0; l < 4; l++) {       // 4096 floats / (256 thr * 4) = 4
            int o = (tid + l * THREADS) * 4;
            cp16(&sB[o], src + o);
        }
    };

    // =========================== PHASE 1 ===================================
    // warps 2x4: wm = wid&1 (rows), wn = wid>>1 (cols); warp tile 16x64
    {
        const int wm = wid & 1;
        const int wn = wid >> 1;

        float acc[8][4];
        #pragma unroll
        for (int j = 0; j < 8; j++)
            #pragma unroll
            for (int c = 0; c < 4; c++) acc[j][c] = 0.f;

        const int nt1 = K1 / BK;   // 24
        #pragma unroll
        for (int s = 0; s < STAGES - 1; s++) {
            issueA(s, s); issueB(W1p, s, s);
            asm volatile("cp.async.commit_group;");
        }

        const int rb = wm * 16 + grp;
        for (int t = 0; t < nt1; t++) {
            asm volatile("cp.async.wait_group %0;" :: "n"(STAGES - 2));
            __syncthreads();
            const int nt = t + STAGES - 1;
            if (nt < nt1) { issueA(nt, nt % STAGES); issueB(W1p, nt, nt % STAGES); }
            asm volatile("cp.async.commit_group;");

            const float* sA = sAb + (t % STAGES) * A_SZ;
            const float* sB = sBb + (t % STAGES) * B_SZ;
            #pragma unroll
            for (int ks = 0; ks < 2; ks++) {
                uint32_t a0 = __float_as_uint(sA[(rb + 0) * SAS + ks * 8 + tg]);
                uint32_t a1 = __float_as_uint(sA[(rb + 8) * SAS + ks * 8 + tg]);
                uint32_t a2 = __float_as_uint(sA[(rb + 0) * SAS + ks * 8 + tg + 4]);
                uint32_t a3 = __float_as_uint(sA[(rb + 8) * SAS + ks * 8 + tg + 4]);
                #pragma unroll
                for (int jl = 0; jl < 8; jl++) {
                    const int j = wn * 8 + jl;
                    float2 b = *(const float2*)(&sB[((ks * 32 + j) << 6) + lane * 2]);
                    mma_tf32(acc[jl], a0, a1, a2, a3,
                             __float_as_uint(b.x), __float_as_uint(b.y));
                }
            }
        }

        asm volatile("cp.async.wait_group 0;");

        // epilogue 1: bias + relu + tf32 -> sN
        #pragma unroll
        for (int jl = 0; jl < 8; jl++) {
            const int c = wn * 64 + jl * 8 + tg * 2;
            const float b0 = b1g[c], b1v = b1g[c + 1];
            float2 v0, v1;
            v0.x = cvt_tf32(fmaxf(acc[jl][0] + b0, 0.f));
            v0.y = cvt_tf32(fmaxf(acc[jl][1] + b1v, 0.f));
            v1.x = cvt_tf32(fmaxf(acc[jl][2] + b0, 0.f));
            v1.y = cvt_tf32(fmaxf(acc[jl][3] + b1v, 0.f));
            *(float2*)(&sN[(rb + 0) * SN + c]) = v0;
            *(float2*)(&sN[(rb + 8) * SN + c]) = v1;
        }
        __syncthreads();
    }

    // =========================== PHASE 2 ===================================
    // 16 pairs x 256; warps 1x8 (wn2 = wid); warp tile 16x32 (NF=4)
    // A(p,k) = sN[(2p + (k>=256)) * SN + (k&255)]
    {
        const int wn2 = wid;

        float acc[4][4];
        #pragma unroll
        for (int j = 0; j < 4; j++)
            #pragma unroll
            for (int c = 0; c < 4; c++) acc[j][c] = 0.f;

        const int nt2 = K2 / BK;   // 32
        #pragma unroll
        for (int s = 0; s < STAGES - 1; s++) {
            issueB(Wrp, s, s);
            asm volatile("cp.async.commit_group;");
        }

        for (int t = 0; t < nt2; t++) {
            asm volatile("cp.async.wait_group %0;" :: "n"(STAGES - 2));
            __syncthreads();
            const int nt = t + STAGES - 1;
            if (nt < nt2) issueB(Wrp, nt, nt % STAGES);
            asm volatile("cp.async.commit_group;");

            const float* sB = sBb + (t % STAGES) * B_SZ;
            #pragma unroll
            for (int ks = 0; ks < 2; ks++) {
                const int k  = t * BK + ks * 8;
                const int h  = (k >= 256) ? 1 : 0;
                const int kk = k & 255;
                uint32_t a0 = __float_as_uint(sN[(2 * (grp + 0) + h) * SN + kk + tg]);
                uint32_t a1 = __float_as_uint(sN[(2 * (grp + 8) + h) * SN + kk + tg]);
                uint32_t a2 = __float_as_uint(sN[(2 * (grp + 0) + h) * SN + kk + tg + 4]);
                uint32_t a3 = __float_as_uint(sN[(2 * (grp + 8) + h) * SN + kk + tg + 4]);
                #pragma unroll
                for (int jl = 0; jl < 4; jl++) {
                    const int j = wn2 * 4 + jl;
                    float2 b = *(const float2*)(&sB[((ks * 32 + j) << 6) + lane * 2]);
                    mma_tf32(acc[jl], a0, a1, a2, a3,
                             __float_as_uint(b.x), __float_as_uint(b.y));
                }
            }
        }

        // epilogue 2: bias + relu -> gmem
        const int prow = by * 16 + grp;
        #pragma unroll
        for (int jl = 0; jl < 4; jl++) {
            const int c = wn2 * 32 + jl * 8 + tg * 2;
            const float b0 = br[c], b1v = br[c + 1];
            float2 v0, v1;
            v0.x = fmaxf(acc[jl][0] + b0, 0.f);
            v0.y = fmaxf(acc[jl][1] + b1v, 0.f);
            v1.x = fmaxf(acc[jl][2] + b0, 0.f);
            v1.y = fmaxf(acc[jl][3] + b1v, 0.f);
            *(float2*)(out + (size_t)(prow + 0) * H + c) = v0;
            *(float2*)(out + (size_t)(prow + 8) * H + c) = v1;
        }
    }
}

// ---------------------------------------------------------------------------
extern "C" void kernel_launch(void* const* d_in, const int* in_sizes, int n_in,
                              void* d_out, int out_size) {
    const float* E    = (const float*)d_in[0];
    const float* R    = (const float*)d_in[1];
    const float* Wt   = (const float*)d_in[2];
    const float* bt   = (const float*)d_in[3];
    const float* Wn   = (const float*)d_in[4];
    const float* bn   = (const float*)d_in[5];
    const float* Wr   = (const float*)d_in[6];
    const float* br   = (const float*)d_in[7];
    const int*   ents = (const int*)d_in[8];
    const int*   nent = (const int*)d_in[9];
    const int*   nrel = (const int*)d_in[10];
    const int*   offs = (const int*)d_in[11];
    float* out = (float*)d_out;

    float *A1, *W1p, *Wrp, *b1;
    cudaGetSymbolAddress((void**)&A1,  g_A1);
    cudaGetSymbolAddress((void**)&W1p, g_W1p);
    cudaGetSymbolAddress((void**)&Wrp, g_Wrp);
    cudaGetSymbolAddress((void**)&b1,  g_b1);

    cudaFuncSetAttribute(fused_mlp,
                         cudaFuncAttributeMaxDynamicSharedMemorySize, FUSED_SMEM);

    // 1) gather + segment mean (+ fused weight pack), 2 warps/node
    gather_mean<<<NODES / 4, 256>>>(E, R, ents, nent, nrel, offs,
                                    Wt, Wn, Wr, bt, bn);

    // 2+3) fused node-MLP + pair-MLP: 256 CTAs x 256 threads, 2 CTAs/SM
    fused_mlp<<<NODES / BM, 256, FUSED_SMEM>>>(A1, W1p, b1, Wrp, br, out);
}